// round 4
// baseline (speedup 1.0000x reference)
#include <cuda_runtime.h>
#include <cuda_bf16.h>

#define N_STARS 2048
#define BATCH   256
#define PF      28
#define NGE     512
#define GF      32
#define KTOT    60        // PF + GF
#define OPD2    65536     // 256*256

// Scratch (no device allocation allowed -> __device__ globals)
__device__ float g_W[KTOT * BATCH];   // W[k][b], k-major

// ---------------------------------------------------------------------------
// Stage 1: index search + W = [poly_dic[idx] @ alpha_poly | graph_dic[idx] @ alpha_graph]
// One block per query position b. 256 threads.
// ---------------------------------------------------------------------------
__global__ __launch_bounds__(256) void prep_kernel(
    const float* __restrict__ positions, const float* __restrict__ obs_pos,
    const float* __restrict__ poly_dic,  const float* __restrict__ graph_dic,
    const float* __restrict__ alpha_poly,const float* __restrict__ alpha_graph)
{
    int b = blockIdx.x;
    int t = threadIdx.x;

    __shared__ int   s_min;
    __shared__ float s_row[NGE];
    __shared__ float s_prow[PF];
    __shared__ float s_part[8][32];

    if (t == 0) s_min = N_STARS;
    __syncthreads();

    // Faithful to argmax over flattened (N,2) equality: first n where
    // x matches OR y matches (flat_first // 2).
    float px = positions[2 * b], py = positions[2 * b + 1];
    int local = N_STARS;
    for (int n = t; n < N_STARS; n += 256) {
        float ox = obs_pos[2 * n], oy = obs_pos[2 * n + 1];
        if (ox == px || oy == py) { local = n; break; }   // ascending stride -> first hit is thread-min
    }
    if (local < N_STARS) atomicMin(&s_min, local);
    __syncthreads();
    int idx = (s_min < N_STARS) ? s_min : 0;

    // Stage dictionary rows in shared
    for (int g = t; g < NGE; g += 256) s_row[g] = graph_dic[(size_t)idx * NGE + g];
    if (t < PF) s_prow[t] = poly_dic[(size_t)idx * PF + t];
    __syncthreads();

    // Graph GEMV partials: warp `sl` covers g in [sl*64, sl*64+64), lane = output col kg
    {
        int kg = t & 31, sl = t >> 5;
        float acc = 0.f;
        int g0 = sl * 64;
        #pragma unroll 8
        for (int i = 0; i < 64; i++) {
            int g = g0 + i;
            acc += s_row[g] * alpha_graph[g * GF + kg];   // coalesced 128B per g
        }
        s_part[sl][kg] = acc;
    }
    __syncthreads();

    if (t < GF) {
        float acc = 0.f;
        #pragma unroll
        for (int sl = 0; sl < 8; sl++) acc += s_part[sl][t];
        g_W[(PF + t) * BATCH + b] = acc;                  // graph features -> k = 28..59
    } else if (t < GF + PF) {
        int k = t - GF;
        float acc = 0.f;
        #pragma unroll
        for (int p = 0; p < PF; p++) acc += s_prow[p] * alpha_poly[p * PF + k];
        g_W[k * BATCH + b] = acc;                         // poly features -> k = 0..27
    }
}

// ---------------------------------------------------------------------------
// Stage 2: C[b][e] = sum_k W[b][k] * S[k][e]   (B=256, E=65536, K=60)
// CTA tile 64b x 64e, thread micro-tile 4b x 4e, packed f32x2 FMAs.
// ---------------------------------------------------------------------------
__device__ __forceinline__ void ffma2(unsigned long long &d,
                                      unsigned long long a,
                                      unsigned long long b_) {
    asm("fma.rn.f32x2 %0, %1, %2, %0;" : "+l"(d) : "l"(a), "l"(b_));
}

__global__ __launch_bounds__(256) void mccd_main(
    const float* __restrict__ S_poly, const float* __restrict__ S_graph,
    float* __restrict__ out)
{
    __shared__ __align__(16) float              sS[KTOT * 64];  // S[k][e_tile]     15 KB
    __shared__ __align__(16) unsigned long long sW[KTOT * 64];  // (w,w)[k][b_tile] 30 KB

    int tid    = threadIdx.x;
    int e_base = blockIdx.x * 64;
    int b_base = blockIdx.y * 64;

    // Stage S tile and duplicated W tile (whole K fits; single load phase)
    for (int i = tid; i < KTOT * 64; i += 256) {
        int k = i >> 6, j = i & 63;
        sS[i] = (k < PF) ? S_poly [(size_t)k        * OPD2 + e_base + j]
                         : S_graph[(size_t)(k - PF) * OPD2 + e_base + j];
        float w = g_W[k * BATCH + b_base + j];
        float2 wd = make_float2(w, w);
        sW[i] = *reinterpret_cast<unsigned long long*>(&wd);
    }
    __syncthreads();

    int tb = tid >> 4;     // 0..15 -> 4 b rows each
    int te = tid & 15;     // 0..15 -> 4 e cols each

    unsigned long long a00 = 0, a01 = 0, a10 = 0, a11 = 0;
    unsigned long long a20 = 0, a21 = 0, a30 = 0, a31 = 0;

    const float*              sSp = sS + te * 4;   // 16B aligned
    const unsigned long long* sWp = sW + tb * 4;   // 32B aligned

    #pragma unroll
    for (int k = 0; k < KTOT; k++) {
        // All shared accesses are broadcast/conflict-free (same addr per half-warp pair)
        ulonglong2 s   = *reinterpret_cast<const ulonglong2*>(sSp + k * 64);      // (s0,s1)|(s2,s3)
        ulonglong2 w01 = *reinterpret_cast<const ulonglong2*>(sWp + k * 64);      // (w0,w0)|(w1,w1)
        ulonglong2 w23 = *reinterpret_cast<const ulonglong2*>(sWp + k * 64 + 2);  // (w2,w2)|(w3,w3)
        ffma2(a00, w01.x, s.x); ffma2(a01, w01.x, s.y);
        ffma2(a10, w01.y, s.x); ffma2(a11, w01.y, s.y);
        ffma2(a20, w23.x, s.x); ffma2(a21, w23.x, s.y);
        ffma2(a30, w23.y, s.x); ffma2(a31, w23.y, s.y);
    }

    // 128-bit coalesced stores: row stride = OPD2 floats
    size_t row = (size_t)(b_base + tb * 4) * OPD2 + (size_t)e_base + te * 4;
    ulonglong2 v;
    v.x = a00; v.y = a01; *reinterpret_cast<ulonglong2*>(out + row)            = v;
    v.x = a10; v.y = a11; *reinterpret_cast<ulonglong2*>(out + row +     OPD2) = v;
    v.x = a20; v.y = a21; *reinterpret_cast<ulonglong2*>(out + row + 2 * OPD2) = v;
    v.x = a30; v.y = a31; *reinterpret_cast<ulonglong2*>(out + row + 3 * OPD2) = v;
}

// ---------------------------------------------------------------------------
extern "C" void kernel_launch(void* const* d_in, const int* in_sizes, int n_in,
                              void* d_out, int out_size) {
    const float* positions   = (const float*)d_in[0];
    const float* obs_pos     = (const float*)d_in[1];
    const float* poly_dic    = (const float*)d_in[2];
    const float* graph_dic   = (const float*)d_in[3];
    const float* alpha_poly  = (const float*)d_in[4];
    const float* alpha_graph = (const float*)d_in[5];
    const float* S_poly      = (const float*)d_in[6];
    const float* S_graph     = (const float*)d_in[7];
    float* out = (float*)d_out;

    prep_kernel<<<BATCH, 256>>>(positions, obs_pos, poly_dic, graph_dic,
                                alpha_poly, alpha_graph);
    mccd_main<<<dim3(OPD2 / 64, BATCH / 64), 256>>>(S_poly, S_graph, out);
}

// round 6
// speedup vs baseline: 1.9335x; 1.9335x over previous
#include <cuda_runtime.h>
#include <cuda_bf16.h>

#define N_STARS 2048
#define BATCH   256
#define PF      28
#define NGE     512
#define GF      32
#define KTOT    60        // PF + GF
#define OPD2    65536     // 256*256

// Scratch (no device allocation allowed -> __device__ globals)
__device__ float g_W[KTOT * BATCH];   // W[k][b], k-major

// ---------------------------------------------------------------------------
// Stage 1: index search + W = [poly_dic[idx] @ alpha_poly | graph_dic[idx] @ alpha_graph]
// One block per query position b. 256 threads.  (unchanged; passed R3)
// ---------------------------------------------------------------------------
__global__ __launch_bounds__(256) void prep_kernel(
    const float* __restrict__ positions, const float* __restrict__ obs_pos,
    const float* __restrict__ poly_dic,  const float* __restrict__ graph_dic,
    const float* __restrict__ alpha_poly,const float* __restrict__ alpha_graph)
{
    int b = blockIdx.x;
    int t = threadIdx.x;

    __shared__ int   s_min;
    __shared__ float s_row[NGE];
    __shared__ float s_prow[PF];
    __shared__ float s_part[8][32];

    if (t == 0) s_min = N_STARS;
    __syncthreads();

    // Faithful to argmax over flattened (N,2) equality: first n where
    // x matches OR y matches (flat_first // 2).
    float px = positions[2 * b], py = positions[2 * b + 1];
    int local = N_STARS;
    for (int n = t; n < N_STARS; n += 256) {
        float ox = obs_pos[2 * n], oy = obs_pos[2 * n + 1];
        if (ox == px || oy == py) { local = n; break; }   // ascending stride -> first hit is thread-min
    }
    if (local < N_STARS) atomicMin(&s_min, local);
    __syncthreads();
    int idx = (s_min < N_STARS) ? s_min : 0;

    // Stage dictionary rows in shared
    for (int g = t; g < NGE; g += 256) s_row[g] = graph_dic[(size_t)idx * NGE + g];
    if (t < PF) s_prow[t] = poly_dic[(size_t)idx * PF + t];
    __syncthreads();

    // Graph GEMV partials: warp `sl` covers g in [sl*64, sl*64+64), lane = output col kg
    {
        int kg = t & 31, sl = t >> 5;
        float acc = 0.f;
        int g0 = sl * 64;
        #pragma unroll 8
        for (int i = 0; i < 64; i++) {
            int g = g0 + i;
            acc += s_row[g] * alpha_graph[g * GF + kg];   // coalesced 128B per g
        }
        s_part[sl][kg] = acc;
    }
    __syncthreads();

    if (t < GF) {
        float acc = 0.f;
        #pragma unroll
        for (int sl = 0; sl < 8; sl++) acc += s_part[sl][t];
        g_W[(PF + t) * BATCH + b] = acc;                  // graph features -> k = 28..59
    } else if (t < GF + PF) {
        int k = t - GF;
        float acc = 0.f;
        #pragma unroll
        for (int p = 0; p < PF; p++) acc += s_prow[p] * alpha_poly[p * PF + k];
        g_W[k * BATCH + b] = acc;                         // poly features -> k = 0..27
    }
}

// ---------------------------------------------------------------------------
// Stage 2: C[b][e] = sum_k W[b][k] * S[k][e]   (B=256, E=65536, K=60)
// CTA tile 128e x 128b. Thread micro-tile 8e x 8b (32 FFMA2 per thread per k).
// Pair-swap trick: acc_diag pairs (e0b0,e1b1) use natural W pairs,
// acc_cross pairs (e0b1,e1b0) use pair-swapped W array. No operand duplication,
// all LDS.128 on naturally packed floats, bank-conflict-free via S chunk padding.
// ---------------------------------------------------------------------------
#define S_ROW   192                 // 16 chunks * 12 floats (8 data + 4 pad)
#define SMEM_FLOATS (KTOT*S_ROW + 2*KTOT*128)
#define SMEM_BYTES  (SMEM_FLOATS * 4)   // 107520

typedef unsigned long long ull;

__device__ __forceinline__ void ffma2(ull &d, ull a, ull b_) {
    asm("fma.rn.f32x2 %0, %1, %2, %0;" : "+l"(d) : "l"(a), "l"(b_));
}
__device__ __forceinline__ float2 u2f(ull u) {
    float2 f;
    asm("mov.b64 {%0,%1}, %2;" : "=f"(f.x), "=f"(f.y) : "l"(u));
    return f;
}

__global__ void __launch_bounds__(256, 2) mccd_main(
    const float* __restrict__ S_poly, const float* __restrict__ S_graph,
    float* __restrict__ out)
{
    extern __shared__ float smem[];
    float* sS  = smem;                      // [KTOT][192] padded chunks
    float* sWn = smem + KTOT * S_ROW;       // [KTOT][128] natural
    float* sWs = sWn  + KTOT * 128;         // [KTOT][128] pair-swapped

    int tid    = threadIdx.x;
    int e_base = blockIdx.x * 128;
    int b_base = blockIdx.y * 128;

    // ---- stage (coalesced global reads; whole K fits, single phase) ----
    for (int idx = tid; idx < KTOT * 128; idx += 256) {
        int k = idx >> 7, j = idx & 127;
        float sv = (k < PF) ? S_poly [(size_t)k        * OPD2 + e_base + j]
                            : S_graph[(size_t)(k - PF) * OPD2 + e_base + j];
        sS[k * S_ROW + (j >> 3) * 12 + (j & 7)] = sv;
        float w = g_W[k * BATCH + b_base + j];
        sWn[k * 128 + j]       = w;
        sWs[k * 128 + (j ^ 1)] = w;
    }
    __syncthreads();

    int lane = tid & 31, wid = tid >> 5;
    int we = wid & 1, wb = wid >> 1;        // warp grid: 2 e-warps x 4 b-warps
    int eg = lane & 7, bg = lane >> 3;      // lane grid: 8 e-groups x 4 b-groups

    const float* sp  = sS  + (we * 8 + eg) * 12;      // 48B chunk stride -> conflict-free
    const float* wpn = sWn + (wb * 4 + bg) * 8;       // 32B stride, 4 distinct -> conflict-free
    const float* wps = sWs + (wb * 4 + bg) * 8;

    ull ad[4][4] = {}, ax[4][4] = {};       // diag / cross accumulator pairs

    #pragma unroll 12
    for (int k = 0; k < KTOT; k++) {
        ulonglong2 sA = *reinterpret_cast<const ulonglong2*>(sp  + k * S_ROW);
        ulonglong2 sB = *reinterpret_cast<const ulonglong2*>(sp  + k * S_ROW + 4);
        ulonglong2 nA = *reinterpret_cast<const ulonglong2*>(wpn + k * 128);
        ulonglong2 nB = *reinterpret_cast<const ulonglong2*>(wpn + k * 128 + 4);
        ulonglong2 xA = *reinterpret_cast<const ulonglong2*>(wps + k * 128);
        ulonglong2 xB = *reinterpret_cast<const ulonglong2*>(wps + k * 128 + 4);
        ull su[4] = { sA.x, sA.y, sB.x, sB.y };   // (s0,s1)(s2,s3)(s4,s5)(s6,s7)
        ull wn[4] = { nA.x, nA.y, nB.x, nB.y };   // (w0,w1)(w2,w3)...
        ull ws[4] = { xA.x, xA.y, xB.x, xB.y };   // (w1,w0)(w3,w2)...
        #pragma unroll
        for (int p = 0; p < 4; p++) {
            #pragma unroll
            for (int q = 0; q < 4; q++) {
                ffma2(ad[p][q], su[p], wn[q]);    // (e2p,b2q) , (e2p+1,b2q+1)
                ffma2(ax[p][q], su[p], ws[q]);    // (e2p,b2q+1), (e2p+1,b2q)
            }
        }
    }

    // ---- epilogue: unscramble diag/cross pairs, 128-bit coalesced-ish stores ----
    int e0 = e_base + we * 64 + eg * 8;
    int b0 = b_base + wb * 32 + bg * 8;
    #pragma unroll
    for (int q = 0; q < 4; q++) {
        float* r0 = out + (size_t)(b0 + 2 * q)     * OPD2 + e0;  // even b row
        float* r1 = out + (size_t)(b0 + 2 * q + 1) * OPD2 + e0;  // odd  b row
        float v[8], u[8];
        #pragma unroll
        for (int p = 0; p < 4; p++) {
            float2 d = u2f(ad[p][q]);   // (c[e2p,b2q]  , c[e2p+1,b2q+1])
            float2 x = u2f(ax[p][q]);   // (c[e2p,b2q+1], c[e2p+1,b2q]  )
            v[2 * p] = d.x;  v[2 * p + 1] = x.y;
            u[2 * p] = x.x;  u[2 * p + 1] = d.y;
        }
        *reinterpret_cast<float4*>(r0)     = make_float4(v[0], v[1], v[2], v[3]);
        *reinterpret_cast<float4*>(r0 + 4) = make_float4(v[4], v[5], v[6], v[7]);
        *reinterpret_cast<float4*>(r1)     = make_float4(u[0], u[1], u[2], u[3]);
        *reinterpret_cast<float4*>(r1 + 4) = make_float4(u[4], u[5], u[6], u[7]);
    }
}

// ---------------------------------------------------------------------------
extern "C" void kernel_launch(void* const* d_in, const int* in_sizes, int n_in,
                              void* d_out, int out_size) {
    const float* positions   = (const float*)d_in[0];
    const float* obs_pos     = (const float*)d_in[1];
    const float* poly_dic    = (const float*)d_in[2];
    const float* graph_dic   = (const float*)d_in[3];
    const float* alpha_poly  = (const float*)d_in[4];
    const float* alpha_graph = (const float*)d_in[5];
    const float* S_poly      = (const float*)d_in[6];
    const float* S_graph     = (const float*)d_in[7];
    float* out = (float*)d_out;

    cudaFuncSetAttribute(mccd_main, cudaFuncAttributeMaxDynamicSharedMemorySize,
                         SMEM_BYTES);

    prep_kernel<<<BATCH, 256>>>(positions, obs_pos, poly_dic, graph_dic,
                                alpha_poly, alpha_graph);
    mccd_main<<<dim3(OPD2 / 128, BATCH / 128), 256, SMEM_BYTES>>>(S_poly, S_graph, out);
}